// round 1
// baseline (speedup 1.0000x reference)
#include <cuda_runtime.h>
#include <cstdint>

// 2-layer LSTM, H=6, F=6, B=4096, T=1024.
// One warp per batch element; lane j (j<24) owns gate row j (PyTorch order i,f,g,o).
// Weights pre-scaled by -log2(e)*s so activation is ex2/rcp only.

#define WARPS_PER_BLOCK 8
#define THREADS (WARPS_PER_BLOCK * 32)
#define T_LEN 1024
#define TCHUNK 32                  // timesteps staged per smem round
#define CHUNK_FLOATS (TCHUNK * 6)  // 192

__device__ __forceinline__ float ex2f(float x) {
    float y; asm("ex2.approx.f32 %0, %1;" : "=f"(y) : "f"(x)); return y;
}
__device__ __forceinline__ float rcpf(float x) {
    float y; asm("rcp.approx.f32 %0, %1;" : "=f"(y) : "f"(x)); return y;
}

__global__ __launch_bounds__(THREADS)
void lstm2_kernel(const float* __restrict__ x,
                  const float* __restrict__ wih0, const float* __restrict__ whh0,
                  const float* __restrict__ bih0, const float* __restrict__ bhh0,
                  const float* __restrict__ wih1, const float* __restrict__ whh1,
                  const float* __restrict__ bih1, const float* __restrict__ bhh1,
                  float* __restrict__ out)
{
    __shared__ float sx[WARPS_PER_BLOCK][CHUNK_FLOATS];
    __shared__ float so[WARPS_PER_BLOCK][CHUNK_FLOATS];

    const int lane = threadIdx.x & 31;
    const int warp = threadIdx.x >> 5;
    const int b = blockIdx.x * WARPS_PER_BLOCK + warp;

    const bool is_g = (lane >= 12 && lane < 18);       // tanh gate rows
    const float scale = is_g ? -2.8853900817779268f    // -2*log2(e)
                             : -1.4426950408889634f;   // -log2(e)
    const float Aact = is_g ? 2.0f : 1.0f;
    const float Bact = is_g ? -1.0f : 0.0f;

    // Per-lane weight rows (pre-scaled). Lanes >=24 replicate row 0 (harmless).
    const int j = (lane < 24) ? lane : 0;
    float wi0[6], wh0[6], wi1[6], wh1[6];
#pragma unroll
    for (int k = 0; k < 6; k++) {
        wi0[k] = wih0[j * 6 + k] * scale;
        wh0[k] = whh0[j * 6 + k] * scale;
        wi1[k] = wih1[j * 6 + k] * scale;
        wh1[k] = whh1[j * 6 + k] * scale;
    }
    const float bias0 = (bih0[j] + bhh0[j]) * scale;
    const float bias1 = (bih1[j] + bhh1[j]) * scale;

    float hb0[6], hb1[6];
#pragma unroll
    for (int k = 0; k < 6; k++) { hb0[k] = 0.0f; hb1[k] = 0.0f; }
    float c0 = 0.0f, c1 = 0.0f;

    const float* xb = x + (size_t)b * (T_LEN * 6);
    float* ob = out + (size_t)b * (T_LEN * 6);

    for (int t0 = 0; t0 < T_LEN; t0 += TCHUNK) {
        // ---- stage 192 input floats (32 steps x 6) via coalesced float4 ----
        {
            const float4* src = reinterpret_cast<const float4*>(xb + t0 * 6);
            float4* dst = reinterpret_cast<float4*>(sx[warp]);
            dst[lane] = src[lane];                       // 32 float4 = 128 floats
            if (lane < 16) dst[32 + lane] = src[32 + lane];  // remaining 64
        }
        __syncwarp();

#pragma unroll 2
        for (int dt = 0; dt < TCHUNK; dt++) {
            const float* xr = &sx[warp][dt * 6];

            // ================= layer 0 =================
            float za = bias0, zb = 0.0f;
#pragma unroll
            for (int k = 0; k < 6; k++) {
                za = fmaf(wi0[k], xr[k], za);
                zb = fmaf(wh0[k], hb0[k], zb);
            }
            float a = fmaf(Aact, rcpf(1.0f + ex2f(za + zb)), Bact);

            float ig = a;
            float fg = __shfl_sync(0xffffffffu, a, (lane + 6) & 31);
            float gg = __shfl_sync(0xffffffffu, a, (lane + 12) & 31);
            float og = __shfl_sync(0xffffffffu, a, (lane + 18) & 31);
            c0 = fmaf(fg, c0, ig * gg);
            float tc = fmaf(2.0f, rcpf(1.0f + ex2f(c0 * -2.8853900817779268f)), -1.0f);
            float h = og * tc;   // valid on lanes 0..5 (element's h[lane])
#pragma unroll
            for (int k = 0; k < 6; k++)
                hb0[k] = __shfl_sync(0xffffffffu, h, k);

            // ================= layer 1 =================
            za = bias1; zb = 0.0f;
#pragma unroll
            for (int k = 0; k < 6; k++) {
                za = fmaf(wi1[k], hb0[k], za);
                zb = fmaf(wh1[k], hb1[k], zb);
            }
            a = fmaf(Aact, rcpf(1.0f + ex2f(za + zb)), Bact);

            ig = a;
            fg = __shfl_sync(0xffffffffu, a, (lane + 6) & 31);
            gg = __shfl_sync(0xffffffffu, a, (lane + 12) & 31);
            og = __shfl_sync(0xffffffffu, a, (lane + 18) & 31);
            c1 = fmaf(fg, c1, ig * gg);
            tc = fmaf(2.0f, rcpf(1.0f + ex2f(c1 * -2.8853900817779268f)), -1.0f);
            float h2 = og * tc;
#pragma unroll
            for (int k = 0; k < 6; k++)
                hb1[k] = __shfl_sync(0xffffffffu, h2, k);

            if (lane < 6) so[warp][dt * 6 + lane] = h2;
        }
        __syncwarp();

        // ---- flush 192 output floats via coalesced float4 ----
        {
            float4* dst = reinterpret_cast<float4*>(ob + t0 * 6);
            const float4* src = reinterpret_cast<const float4*>(so[warp]);
            dst[lane] = src[lane];
            if (lane < 16) dst[32 + lane] = src[32 + lane];
        }
        __syncwarp();
    }
}

extern "C" void kernel_launch(void* const* d_in, const int* in_sizes, int n_in,
                              void* d_out, int out_size)
{
    const float* x    = (const float*)d_in[0];
    const float* wih0 = (const float*)d_in[1];
    const float* whh0 = (const float*)d_in[2];
    const float* bih0 = (const float*)d_in[3];
    const float* bhh0 = (const float*)d_in[4];
    const float* wih1 = (const float*)d_in[5];
    const float* whh1 = (const float*)d_in[6];
    const float* bih1 = (const float*)d_in[7];
    const float* bhh1 = (const float*)d_in[8];
    float* out = (float*)d_out;

    const int B = in_sizes[0] / (T_LEN * 6);       // 4096
    const int grid = B / WARPS_PER_BLOCK;          // 512

    lstm2_kernel<<<grid, THREADS>>>(x, wih0, whh0, bih0, bhh0,
                                    wih1, whh1, bih1, bhh1, out);
}

// round 2
// speedup vs baseline: 1.6875x; 1.6875x over previous
#include <cuda_runtime.h>
#include <cstdint>

// 2-layer LSTM, H=6, F=6, B=4096, T=1024.
// 4 batch elements per warp; within each 8-lane segment, lane k (k<6) owns
// hidden index k and computes ALL FOUR gate rows (i,f,g,o) for that k.
// No gate-gather shuffles; only 6 segment-broadcasts of h per layer.
// Weights pre-scaled by -log2(e) (sigmoid rows) / -2log2(e) (tanh rows) so
// every activation is ex2.approx + add + rcp.approx (+fma for tanh).

#define WARPS_PER_BLOCK 4
#define THREADS (WARPS_PER_BLOCK * 32)
#define ELEMS_PER_WARP 4
#define T_LEN 1024
#define TCHUNK 32
#define CDATA  (TCHUNK * 6)   // 192 floats of real data per element-chunk
#define CSTRIDE 200           // padded stride (floats): 200 % 32 = 8 -> conflict-free
#define CSTRIDE4 (CSTRIDE / 4)

#define L2E  1.4426950408889634f

__device__ __forceinline__ float ex2f(float x) {
    float y; asm("ex2.approx.f32 %0, %1;" : "=f"(y) : "f"(x)); return y;
}
__device__ __forceinline__ float rcpf(float x) {
    float y; asm("rcp.approx.f32 %0, %1;" : "=f"(y) : "f"(x)); return y;
}
// sigmoid(z) where z already pre-scaled by -log2(e)
__device__ __forceinline__ float sigp(float zs) {
    return rcpf(1.0f + ex2f(zs));
}
// tanh(z) where z already pre-scaled by -2*log2(e)
__device__ __forceinline__ float tanhp(float zs) {
    return fmaf(2.0f, rcpf(1.0f + ex2f(zs)), -1.0f);
}

__global__ __launch_bounds__(THREADS, 1)
void lstm2_kernel(const float* __restrict__ x,
                  const float* __restrict__ wih0, const float* __restrict__ whh0,
                  const float* __restrict__ bih0, const float* __restrict__ bhh0,
                  const float* __restrict__ wih1, const float* __restrict__ whh1,
                  const float* __restrict__ bih1, const float* __restrict__ bhh1,
                  float* __restrict__ out)
{
    __shared__ float sx[WARPS_PER_BLOCK][ELEMS_PER_WARP * CSTRIDE];
    __shared__ float so[WARPS_PER_BLOCK][ELEMS_PER_WARP * CSTRIDE];

    const int lane = threadIdx.x & 31;
    const int warp = threadIdx.x >> 5;
    const int e    = lane >> 3;        // element within warp (0..3)
    const int s    = lane & 7;         // sub-lane within element segment
    const int k    = (s < 6) ? s : 0;  // hidden index owned by this lane

    const int b0 = (blockIdx.x * WARPS_PER_BLOCK + warp) * ELEMS_PER_WARP;

    // ---- per-lane weights: 4 gate rows (i,f,g,o) of hidden index k, pre-scaled ----
    // rows: i=k, f=6+k, g=12+k, o=18+k
    float wiA[4][6], whA[4][6], wiB[4][6], whB[4][6];
    float bA[4], bB[4];
#pragma unroll
    for (int g = 0; g < 4; g++) {
        const float sc = (g == 2) ? (-2.0f * L2E) : (-L2E);
        const int row = g * 6 + k;
#pragma unroll
        for (int q = 0; q < 6; q++) {
            wiA[g][q] = wih0[row * 6 + q] * sc;
            whA[g][q] = whh0[row * 6 + q] * sc;
            wiB[g][q] = wih1[row * 6 + q] * sc;
            whB[g][q] = whh1[row * 6 + q] * sc;
        }
        bA[g] = (bih0[row] + bhh0[row]) * sc;
        bB[g] = (bih1[row] + bhh1[row]) * sc;
    }

    float hb0[6], hb1[6];
#pragma unroll
    for (int q = 0; q < 6; q++) { hb0[q] = 0.0f; hb1[q] = 0.0f; }
    float c0 = 0.0f, c1 = 0.0f;

    for (int t0 = 0; t0 < T_LEN; t0 += TCHUNK) {
        // ---- stage 4 elements x 192 floats via coalesced float4 ----
        {
            float4* dst = reinterpret_cast<float4*>(sx[warp]);
#pragma unroll
            for (int i = 0; i < 6; i++) {
                int idx = i * 32 + lane;          // 0..191  (192 float4 total)
                int ee  = idx / 48;               // element
                int off = idx - ee * 48;          // float4 offset within element
                const float4* src = reinterpret_cast<const float4*>(
                    x + (size_t)(b0 + ee) * (T_LEN * 6) + t0 * 6);
                dst[ee * CSTRIDE4 + off] = src[off];
            }
        }
        __syncwarp();

#pragma unroll 1
        for (int dt = 0; dt < TCHUNK; dt++) {
            const float* xr = &sx[warp][e * CSTRIDE + dt * 6];

            // ================= layer 0 =================
            float zi = bA[0], zf = bA[1], zg = bA[2], zo = bA[3];
#pragma unroll
            for (int q = 0; q < 6; q++) {
                const float xv = xr[q], hv = hb0[q];
                zi = fmaf(wiA[0][q], xv, zi);  zi = fmaf(whA[0][q], hv, zi);
                zf = fmaf(wiA[1][q], xv, zf);  zf = fmaf(whA[1][q], hv, zf);
                zg = fmaf(wiA[2][q], xv, zg);  zg = fmaf(whA[2][q], hv, zg);
                zo = fmaf(wiA[3][q], xv, zo);  zo = fmaf(whA[3][q], hv, zo);
            }
            {
                const float ig = sigp(zi), fg = sigp(zf), gg = tanhp(zg), og = sigp(zo);
                c0 = fmaf(fg, c0, ig * gg);
                const float h = og * tanhp(c0 * (-2.0f * L2E));
#pragma unroll
                for (int q = 0; q < 6; q++)
                    hb0[q] = __shfl_sync(0xffffffffu, h, q, 8);
            }

            // ================= layer 1 =================
            zi = bB[0]; zf = bB[1]; zg = bB[2]; zo = bB[3];
#pragma unroll
            for (int q = 0; q < 6; q++) {
                const float xv = hb0[q], hv = hb1[q];
                zi = fmaf(wiB[0][q], xv, zi);  zi = fmaf(whB[0][q], hv, zi);
                zf = fmaf(wiB[1][q], xv, zf);  zf = fmaf(whB[1][q], hv, zf);
                zg = fmaf(wiB[2][q], xv, zg);  zg = fmaf(whB[2][q], hv, zg);
                zo = fmaf(wiB[3][q], xv, zo);  zo = fmaf(whB[3][q], hv, zo);
            }
            {
                const float ig = sigp(zi), fg = sigp(zf), gg = tanhp(zg), og = sigp(zo);
                c1 = fmaf(fg, c1, ig * gg);
                const float h2 = og * tanhp(c1 * (-2.0f * L2E));
#pragma unroll
                for (int q = 0; q < 6; q++)
                    hb1[q] = __shfl_sync(0xffffffffu, h2, q, 8);
                if (s < 6) so[warp][e * CSTRIDE + dt * 6 + s] = h2;
            }
        }
        __syncwarp();

        // ---- flush 4 elements x 192 floats via coalesced float4 ----
        {
            const float4* src = reinterpret_cast<const float4*>(so[warp]);
#pragma unroll
            for (int i = 0; i < 6; i++) {
                int idx = i * 32 + lane;
                int ee  = idx / 48;
                int off = idx - ee * 48;
                float4* dst = reinterpret_cast<float4*>(
                    out + (size_t)(b0 + ee) * (T_LEN * 6) + t0 * 6);
                dst[off] = src[ee * CSTRIDE4 + off];
            }
        }
        __syncwarp();
    }
}

extern "C" void kernel_launch(void* const* d_in, const int* in_sizes, int n_in,
                              void* d_out, int out_size)
{
    const float* x    = (const float*)d_in[0];
    const float* wih0 = (const float*)d_in[1];
    const float* whh0 = (const float*)d_in[2];
    const float* bih0 = (const float*)d_in[3];
    const float* bhh0 = (const float*)d_in[4];
    const float* wih1 = (const float*)d_in[5];
    const float* whh1 = (const float*)d_in[6];
    const float* bih1 = (const float*)d_in[7];
    const float* bhh1 = (const float*)d_in[8];
    float* out = (float*)d_out;

    const int B = in_sizes[0] / (T_LEN * 6);                       // 4096
    const int grid = B / (WARPS_PER_BLOCK * ELEMS_PER_WARP);       // 256

    lstm2_kernel<<<grid, THREADS>>>(x, wih0, whh0, bih0, bhh0,
                                    wih1, whh1, bih1, bhh1, out);
}